// round 1
// baseline (speedup 1.0000x reference)
#include <cuda_runtime.h>
#include <cuda_bf16.h>
#include <cstddef>

#define N 4096
#define N4 (N / 4)

// ---------------- device scratch (no allocations allowed) ----------------
__device__ __align__(16) float g_bufA[N];
__device__ __align__(16) float g_bufB[N];
__device__ __align__(16) float g_r[N];
__device__ __align__(16) float g_r2[N];
__device__ float  g_sums[3];         // sum(input), sum(a_final), sum(r)
__device__ __align__(16) float4 g_col[N];  // per-column: {decay, P, Q, currb}
__device__ float  g_actX[N];
__device__ float  g_Bn[N];
__device__ float  g_prevb[N];
__device__ float  g_diag[N];

// ---------------- fill r = 1 ----------------
__global__ void k_fill(float* __restrict__ r) {
    int i = blockIdx.x * blockDim.x + threadIdx.x;
    if (i < N) r[i] = 1.0f;
}

// ---------------- y = (b ? b : 0) + scale * J * x ----------------
// one row per block, 128 threads, float4 loads
__global__ void k_matvec(const float* __restrict__ J, const float* __restrict__ x,
                         const float* __restrict__ b, float scale,
                         float* __restrict__ y) {
    int row = blockIdx.x;
    const float4* Jr = reinterpret_cast<const float4*>(J + (size_t)row * N);
    const float4* x4 = reinterpret_cast<const float4*>(x);
    float sum = 0.0f;
#pragma unroll
    for (int k = 0; k < 8; k++) {
        int idx = threadIdx.x + k * 128;
        float4 jv = Jr[idx];
        float4 xv = x4[idx];
        sum += jv.x * xv.x + jv.y * xv.y + jv.z * xv.z + jv.w * xv.w;
    }
#pragma unroll
    for (int off = 16; off > 0; off >>= 1)
        sum += __shfl_down_sync(0xffffffffu, sum, off);
    __shared__ float ws[4];
    if ((threadIdx.x & 31) == 0) ws[threadIdx.x >> 5] = sum;
    __syncthreads();
    if (threadIdx.x == 0) {
        float s = ws[0] + ws[1] + ws[2] + ws[3];
        y[row] = (b ? b[row] : 0.0f) + scale * s;
    }
}

// ---------------- deterministic 3-way sum reduction (single block) ----------------
__global__ void k_reduce(const float* __restrict__ b, const float* __restrict__ a,
                         const float* __restrict__ r) {
    __shared__ float sb[1024], sa[1024], sr[1024];
    int t = threadIdx.x;
    float vb = 0.f, va = 0.f, vr = 0.f;
    for (int i = t; i < N; i += 1024) { vb += b[i]; va += a[i]; vr += r[i]; }
    sb[t] = vb; sa[t] = va; sr[t] = vr;
    __syncthreads();
    for (int s = 512; s > 0; s >>= 1) {
        if (t < s) { sb[t] += sb[t + s]; sa[t] += sa[t + s]; sr[t] += sr[t + s]; }
        __syncthreads();
    }
    if (t == 0) { g_sums[0] = sb[0]; g_sums[1] = sa[0]; g_sums[2] = sr[0]; }
}

// ---------------- fused N-sized kernel: Perron correction + traces + packing ----------------
__global__ void k_vec(const float* __restrict__ a, const float* __restrict__ r,
                      const float* __restrict__ Bpos, const float* __restrict__ Bneg,
                      const float* __restrict__ etainv, const float* __restrict__ Tcnt,
                      const int* __restrict__ prev, const int* __restrict__ curr,
                      float* __restrict__ out_act, float* __restrict__ out_Bpos,
                      float* __restrict__ out_Bneg, float* __restrict__ out_eta,
                      float* __restrict__ out_Tcnt) {
    int i = blockIdx.x * blockDim.x + threadIdx.x;
    if (i >= N) return;

    // rank-1 Perron correction: alpha = (sum(a) - 2*sum(input)) / sum(r)
    float alpha = (g_sums[1] - 2.0f * g_sums[0]) / g_sums[2];
    float act = a[i] - alpha * r[i];
    out_act[i] = act;

    float X = fminf(fmaxf(act, 0.0f), 1.0f);
    float act01 = (X >= 0.99f) ? 1.0f : 0.0f;

    const float lrp = (float)(0.1 / 0.12);
    float Bp = fminf((1.0f - lrp) * Bpos[i] + lrp * 7.0f * act01, 6.0f);
    const float lrn = 0.1f;
    float Bn = (1.0f - lrn) * Bneg[i];  // A_NEG = 0

    float ei = (float)prev[i] + 0.99f * etainv[i];
    out_Bpos[i] = Bp;
    out_Bneg[i] = Bn;
    out_eta[i]  = ei;

    float prevb = (prev[i] > 0) ? 1.0f : 0.0f;
    out_Tcnt[i] = 0.99f * Tcnt[i] + prevb;

    float actX = (X < 0.99f) ? 0.0f : X;
    float Bpe = (Bp < 0.0f) ? 0.0f : Bp;   // UPDATE_MIN = 0
    float Bne = (Bn < 0.0f) ? 0.0f : Bn;
    float eta = 1.0f / ei;
    bool updated = (prev[i] == 1);

    // pack per-column coefficients so the N^2 kernel needs no branch on updated:
    // J_n = clip(decay*J + actX[i]*P[j] + Bn[i]*Q[j]) ; non-updated: decay=1,P=Q=0
    float decay = updated ? (1.0f - eta) : 1.0f;
    float P = updated ? 1.008f * eta * Bpe : 0.0f;    // 0.1 * 10.08
    float Q = updated ? 1.008f * eta * actX : 0.0f;
    float currb = (curr[i] > 0) ? 1.0f : 0.0f;
    g_col[i] = make_float4(decay, P, Q, currb);
    g_actX[i] = actX;
    g_Bn[i] = Bne;
    g_prevb[i] = prevb;
    g_diag[i] = updated ? eta * 0.165f * actX * Bpe : 0.0f;  // 0.1 * 1.65
}

// ---------------- fused N^2 kernel: J_n and real_T_tilde_n ----------------
__global__ void k_big(const float* __restrict__ J, const float* __restrict__ Tt,
                      float* __restrict__ outJ, float* __restrict__ outT) {
    int i = blockIdx.x;
    float actXi = g_actX[i];
    float Bni = g_Bn[i];
    float prevbi = g_prevb[i];
    float diagterm = g_diag[i];
    const float4* J4 = reinterpret_cast<const float4*>(J + (size_t)i * N);
    const float4* T4 = reinterpret_cast<const float4*>(Tt + (size_t)i * N);
    float4* oJ = reinterpret_cast<float4*>(outJ + (size_t)i * N);
    float4* oT = reinterpret_cast<float4*>(outT + (size_t)i * N);

    for (int q = threadIdx.x; q < N4; q += blockDim.x) {
        float4 jv = J4[q];
        float4 tv = T4[q];
        float4 rj, rt;
        int jbase = q * 4;
#pragma unroll
        for (int c = 0; c < 4; c++) {
            int j = jbase + c;
            float4 col = g_col[j];
            float Jx = (&jv.x)[c];
            float v;
            if (j == i)
                v = col.x * Jx + diagterm;
            else
                v = col.x * Jx + actXi * col.y + Bni * col.z;
            v = fminf(fmaxf(v, 0.0f), 1.0f);
            (&rj.x)[c] = v;
            (&rt.x)[c] = 0.99f * (&tv.x)[c] + prevbi * col.w;
        }
        oJ[q] = rj;
        oT[q] = rt;
    }
}

// ---------------- host launcher ----------------
extern "C" void kernel_launch(void* const* d_in, const int* in_sizes, int n_in,
                              void* d_out, int out_size) {
    const float* input  = (const float*)d_in[0];
    const float* J      = (const float*)d_in[1];
    const float* Bpos   = (const float*)d_in[2];
    const float* Bneg   = (const float*)d_in[3];
    const float* etainv = (const float*)d_in[4];
    const float* Tt     = (const float*)d_in[5];
    const float* Tcnt   = (const float*)d_in[6];
    const int*   prev   = (const int*)d_in[7];
    const int*   curr   = (const int*)d_in[8];

    float* out = (float*)d_out;
    float* out_act  = out;                         // N
    float* out_J    = out + N;                     // N*N
    float* out_Bpos = out_J + (size_t)N * N;       // N
    float* out_Bneg = out_Bpos + N;                // N
    float* out_eta  = out_Bneg + N;                // N
    float* out_Tt   = out_eta + N;                 // N*N
    float* out_Tcnt = out_Tt + (size_t)N * N;      // N

    float *dA, *dB, *dR, *dR2;
    cudaGetSymbolAddress((void**)&dA, g_bufA);
    cudaGetSymbolAddress((void**)&dB, g_bufB);
    cudaGetSymbolAddress((void**)&dR, g_r);
    cudaGetSymbolAddress((void**)&dR2, g_r2);

    // --- right Perron vector via power iteration (3 matvecs from ones) ---
    k_fill<<<(N + 255) / 256, 256>>>(dR);
    float* rs = dR; float* rd = dR2;
    for (int k = 0; k < 3; k++) {
        k_matvec<<<N, 128>>>(J, rs, nullptr, 1.0f, rd);
        float* t = rs; rs = rd; rd = t;
    }
    // final r in rs

    // --- fixed point: a_{k+1} = input + 0.5 * J * a_k, a_0 = input (10 iters) ---
    float* xs = dA; float* xd = dB;
    k_matvec<<<N, 128>>>(J, input, input, 0.5f, xs);
    for (int k = 1; k < 10; k++) {
        k_matvec<<<N, 128>>>(J, xs, input, 0.5f, xd);
        float* t = xs; xs = xd; xd = t;
    }
    // final a in xs

    k_reduce<<<1, 1024>>>(input, xs, rs);
    k_vec<<<N / 256, 256>>>(xs, rs, Bpos, Bneg, etainv, Tcnt, prev, curr,
                            out_act, out_Bpos, out_Bneg, out_eta, out_Tcnt);
    k_big<<<N, 256>>>(J, Tt, out_J, out_Tt);
}

// round 2
// speedup vs baseline: 1.5113x; 1.5113x over previous
#include <cuda_runtime.h>
#include <cuda_bf16.h>
#include <cstddef>

#define N 4096
#define N4 (N / 4)

// ---------------- device scratch (no allocations allowed) ----------------
__device__ __align__(16) float g_bufA[N];
__device__ __align__(16) float g_bufB[N];
__device__ __align__(16) float g_r[N];
__device__ __align__(16) float g_r2[N];
__device__ float  g_sums[3];               // sum(input), sum(a_final), sum(r)
__device__ __align__(16) float4 g_col[N];  // per-column: {decay, P, Q, currb}
__device__ float  g_actX[N];
__device__ float  g_Bn[N];
__device__ float  g_prevb[N];
__device__ float  g_diag[N];

// ---------------- dual matvec: yx = b + 0.5*J*x ; yr = J*r (r==1 if first) ---
// one row per block, 128 threads, float4 loads; J read ONCE for both vectors
__global__ void k_matvec2(const float* __restrict__ J, const float* __restrict__ x,
                          const float* __restrict__ r, const float* __restrict__ b,
                          float* __restrict__ yx, float* __restrict__ yr,
                          int first) {
    int row = blockIdx.x;
    const float4* Jr = reinterpret_cast<const float4*>(J + (size_t)row * N);
    const float4* x4 = reinterpret_cast<const float4*>(x);
    const float4* r4 = reinterpret_cast<const float4*>(r);
    float sx = 0.0f, sr = 0.0f;
#pragma unroll
    for (int k = 0; k < 8; k++) {
        int idx = threadIdx.x + k * 128;
        float4 jv = Jr[idx];
        float4 xv = x4[idx];
        sx += jv.x * xv.x + jv.y * xv.y + jv.z * xv.z + jv.w * xv.w;
        if (first) {
            sr += jv.x + jv.y + jv.z + jv.w;
        } else {
            float4 rv = r4[idx];
            sr += jv.x * rv.x + jv.y * rv.y + jv.z * rv.z + jv.w * rv.w;
        }
    }
#pragma unroll
    for (int off = 16; off > 0; off >>= 1) {
        sx += __shfl_down_sync(0xffffffffu, sx, off);
        sr += __shfl_down_sync(0xffffffffu, sr, off);
    }
    __shared__ float wsx[4], wsr[4];
    if ((threadIdx.x & 31) == 0) {
        wsx[threadIdx.x >> 5] = sx;
        wsr[threadIdx.x >> 5] = sr;
    }
    __syncthreads();
    if (threadIdx.x == 0) {
        float tx = wsx[0] + wsx[1] + wsx[2] + wsx[3];
        float tr = wsr[0] + wsr[1] + wsr[2] + wsr[3];
        yx[row] = b[row] + 0.5f * tx;
        yr[row] = tr;
    }
}

// ---------------- deterministic 3-way sum reduction (single block) ----------------
__global__ void k_reduce(const float* __restrict__ b, const float* __restrict__ a,
                         const float* __restrict__ r) {
    __shared__ float sb[1024], sa[1024], sr[1024];
    int t = threadIdx.x;
    float vb = 0.f, va = 0.f, vr = 0.f;
    for (int i = t; i < N; i += 1024) { vb += b[i]; va += a[i]; vr += r[i]; }
    sb[t] = vb; sa[t] = va; sr[t] = vr;
    __syncthreads();
    for (int s = 512; s > 0; s >>= 1) {
        if (t < s) { sb[t] += sb[t + s]; sa[t] += sa[t + s]; sr[t] += sr[t + s]; }
        __syncthreads();
    }
    if (t == 0) { g_sums[0] = sb[0]; g_sums[1] = sa[0]; g_sums[2] = sr[0]; }
}

// ---------------- fused N-sized kernel: Perron correction + traces + packing ----------------
__global__ void k_vec(const float* __restrict__ a, const float* __restrict__ r,
                      const float* __restrict__ Bpos, const float* __restrict__ Bneg,
                      const float* __restrict__ etainv, const float* __restrict__ Tcnt,
                      const int* __restrict__ prev, const int* __restrict__ curr,
                      float* __restrict__ out_act, float* __restrict__ out_Bpos,
                      float* __restrict__ out_Bneg, float* __restrict__ out_eta,
                      float* __restrict__ out_Tcnt) {
    int i = blockIdx.x * blockDim.x + threadIdx.x;
    if (i >= N) return;

    // rank-1 Perron correction: alpha = (sum(a) - 2*sum(input)) / sum(r)
    float alpha = (g_sums[1] - 2.0f * g_sums[0]) / g_sums[2];
    float act = a[i] - alpha * r[i];
    out_act[i] = act;

    float X = fminf(fmaxf(act, 0.0f), 1.0f);
    float act01 = (X >= 0.99f) ? 1.0f : 0.0f;

    const float lrp = (float)(0.1 / 0.12);
    float Bp = fminf((1.0f - lrp) * Bpos[i] + lrp * 7.0f * act01, 6.0f);
    const float lrn = 0.1f;
    float Bn = (1.0f - lrn) * Bneg[i];  // A_NEG = 0

    float ei = (float)prev[i] + 0.99f * etainv[i];
    out_Bpos[i] = Bp;
    out_Bneg[i] = Bn;
    out_eta[i]  = ei;

    float prevb = (prev[i] > 0) ? 1.0f : 0.0f;
    out_Tcnt[i] = 0.99f * Tcnt[i] + prevb;

    float actX = (X < 0.99f) ? 0.0f : X;
    float Bpe = (Bp < 0.0f) ? 0.0f : Bp;   // UPDATE_MIN = 0
    float Bne = (Bn < 0.0f) ? 0.0f : Bn;
    float eta = 1.0f / ei;
    bool updated = (prev[i] == 1);

    // pack per-column coefficients so the N^2 kernel needs no branch on updated:
    // J_n = clip(decay*J + actX[i]*P[j] + Bn[i]*Q[j]) ; non-updated: decay=1,P=Q=0
    float decay = updated ? (1.0f - eta) : 1.0f;
    float P = updated ? 1.008f * eta * Bpe : 0.0f;    // 0.1 * 10.08
    float Q = updated ? 1.008f * eta * actX : 0.0f;
    float currb = (curr[i] > 0) ? 1.0f : 0.0f;
    g_col[i] = make_float4(decay, P, Q, currb);
    g_actX[i] = actX;
    g_Bn[i] = Bne;
    g_prevb[i] = prevb;
    g_diag[i] = updated ? eta * 0.165f * actX * Bpe : 0.0f;  // 0.1 * 1.65
}

// ---------------- fused N^2 kernel: J_n and real_T_tilde_n ----------------
__global__ void k_big(const float* __restrict__ J, const float* __restrict__ Tt,
                      float* __restrict__ outJ, float* __restrict__ outT) {
    int i = blockIdx.x;
    float actXi = g_actX[i];
    float Bni = g_Bn[i];
    float prevbi = g_prevb[i];
    float diagterm = g_diag[i];
    const float4* J4 = reinterpret_cast<const float4*>(J + (size_t)i * N);
    const float4* T4 = reinterpret_cast<const float4*>(Tt + (size_t)i * N);
    float4* oJ = reinterpret_cast<float4*>(outJ + (size_t)i * N);
    float4* oT = reinterpret_cast<float4*>(outT + (size_t)i * N);

    for (int q = threadIdx.x; q < N4; q += blockDim.x) {
        float4 jv = J4[q];
        float4 tv = T4[q];
        float4 rj, rt;
        int jbase = q * 4;
#pragma unroll
        for (int c = 0; c < 4; c++) {
            int j = jbase + c;
            float4 col = g_col[j];
            float Jx = (&jv.x)[c];
            float v;
            if (j == i)
                v = col.x * Jx + diagterm;
            else
                v = col.x * Jx + actXi * col.y + Bni * col.z;
            v = fminf(fmaxf(v, 0.0f), 1.0f);
            (&rj.x)[c] = v;
            (&rt.x)[c] = 0.99f * (&tv.x)[c] + prevbi * col.w;
        }
        oJ[q] = rj;
        oT[q] = rt;
    }
}

// ---------------- host launcher ----------------
extern "C" void kernel_launch(void* const* d_in, const int* in_sizes, int n_in,
                              void* d_out, int out_size) {
    const float* input  = (const float*)d_in[0];
    const float* J      = (const float*)d_in[1];
    const float* Bpos   = (const float*)d_in[2];
    const float* Bneg   = (const float*)d_in[3];
    const float* etainv = (const float*)d_in[4];
    const float* Tt     = (const float*)d_in[5];
    const float* Tcnt   = (const float*)d_in[6];
    const int*   prev   = (const int*)d_in[7];
    const int*   curr   = (const int*)d_in[8];

    float* out = (float*)d_out;
    float* out_act  = out;                         // N
    float* out_J    = out + N;                     // N*N
    float* out_Bpos = out_J + (size_t)N * N;       // N
    float* out_Bneg = out_Bpos + N;                // N
    float* out_eta  = out_Bneg + N;                // N
    float* out_Tt   = out_eta + N;                 // N*N
    float* out_Tcnt = out_Tt + (size_t)N * N;      // N

    float *dA, *dB, *dR, *dR2;
    cudaGetSymbolAddress((void**)&dA, g_bufA);
    cudaGetSymbolAddress((void**)&dB, g_bufB);
    cudaGetSymbolAddress((void**)&dR, g_r);
    cudaGetSymbolAddress((void**)&dR2, g_r2);

    // 4 joint passes: x_{k+1} = input + 0.5*J*x_k (x_0=input),
    //                 r_{k+1} = J*r_k            (r_0=ones, implicit in pass 1)
    // One J read per pass serves both chains.
    k_matvec2<<<N, 128>>>(J, input, dR /*unused*/, input, dA, dR, 1);
    k_matvec2<<<N, 128>>>(J, dA, dR, input, dB, dR2, 0);
    k_matvec2<<<N, 128>>>(J, dB, dR2, input, dA, dR, 0);
    k_matvec2<<<N, 128>>>(J, dA, dR, input, dB, dR2, 0);
    // final a in dB, final r in dR2

    k_reduce<<<1, 1024>>>(input, dB, dR2);
    k_vec<<<N / 256, 256>>>(dB, dR2, Bpos, Bneg, etainv, Tcnt, prev, curr,
                            out_act, out_Bpos, out_Bneg, out_eta, out_Tcnt);
    k_big<<<N, 256>>>(J, Tt, out_J, out_Tt);
}